// round 15
// baseline (speedup 1.0000x reference)
#include <cuda_runtime.h>
#include <cuda_bf16.h>

// HybridQuanvolutionFraudNet — reference ends with log_softmax over a
// singleton axis ([B,1]): x - logsumexp(x) == 0 elementwise when the axis has
// size 1, for ANY input. The entire quanvolution + MLP pipeline is
// algebraically dead. Exact output: zeros([2048,1], float32); rel_err = 0 on
// every seed.
//
// Perf status — floor fully mapped over 10 rounds. TERMINAL KERNEL.
//   * kernel-node replay cost is body-invariant: four structurally different
//     bodies all measure 3.2-3.7 us kernel time, every pipe ~0%.
//   * memset graph node is SLOWER (6.66 us): CE fill loses at 8 KB.
//   * bench dur for THIS exact body across seven clean runs:
//     4.608, 4.608, 5.600, 4.864, 6.016, 5.728, 4.832 us
//     => ~4.6 us floor, +-1.5 us environmental jitter; ncu kernel time itself
//     drifts 3.2-3.7 us for byte-identical SASS.
//   * No removable work remains: one wave, 16 warps, one STG.E.128 each
//     writing the exact 8192-byte output. Expected value of any edit: zero.

__global__ void __launch_bounds__(512, 1)
HybridQuanvolutionFraudNet_65481071399590_kernel(float4* __restrict__ out, int n4) {
    int i = threadIdx.x;
    if (i < n4) out[i] = make_float4(0.f, 0.f, 0.f, 0.f);  // 512 x STG.E.128 = 8192 B
}

// Defensive fallback for a non-multiple-of-4 out_size (not expected here).
__global__ void HybridQuanvolutionFraudNet_65481071399590_zero_any(float* __restrict__ out, int n) {
    int i = blockIdx.x * blockDim.x + threadIdx.x;
    if (i < n) out[i] = 0.0f;
}

extern "C" void kernel_launch(void* const* d_in, const int* in_sizes, int n_in,
                              void* d_out, int out_size) {
    (void)d_in; (void)in_sizes; (void)n_in;
    if ((out_size & 3) == 0 && out_size <= 4 * 512) {
        HybridQuanvolutionFraudNet_65481071399590_kernel<<<1, 512>>>((float4*)d_out, out_size / 4);
    } else {
        int threads = 256;
        int blocks = (out_size + threads - 1) / threads;
        HybridQuanvolutionFraudNet_65481071399590_zero_any<<<blocks, threads>>>((float*)d_out, out_size);
    }
}